// round 4
// baseline (speedup 1.0000x reference)
#include <cuda_runtime.h>
#include <math.h>

typedef unsigned long long u64;
#define FULL 0xFFFFFFFFu

// ---------------- f32x2 helpers (packed fp32 FMA, 2x FFMA rate on sm_103a) ----
__device__ __forceinline__ void ffma2(u64 &d, u64 a, u64 b){
    asm("fma.rn.f32x2 %0, %1, %2, %0;" : "+l"(d) : "l"(a), "l"(b));
}
__device__ __forceinline__ u64 pk2(float a, float b){
    u64 r; asm("mov.b64 %0, {%1, %2};" : "=l"(r) : "f"(a), "f"(b)); return r;
}
__device__ __forceinline__ float2 up2(u64 v){
    float2 f; asm("mov.b64 {%0, %1}, %2;" : "=f"(f.x), "=f"(f.y) : "l"(v)); return f;
}
union F4U { float4 f; u64 u[2]; };

// ---------------- scratch (device globals; no allocs allowed) ----------------
// imgs=16, mid=128ch, low 128x128, high 256x256, heads=16, logits oc=32
__device__ float g_tr[(size_t)16*128*128*64];    // lowres transposed (n,y,x,ci)      67MB
__device__ float g_tl[(size_t)16*128*128*128];   // conv1 out low-res (n,y,x,c)      134MB
__device__ float g_r [(size_t)16*256*256*128];   // gelu out (n,h,w,c)               537MB
__device__ float g_lg[(size_t)16*32*256*256];    // conv2 logits (n,o,h,w)           134MB
__device__ float g_gx[(size_t)16*16*256*256];    // sample x coord (pixels)           67MB
__device__ float g_gy[(size_t)16*16*256*256];    // sample y coord (pixels)           67MB
__device__ float g_p1[16*256*128];               // per-row channel sums
__device__ float g_p2[16*256*128];               // per-row channel sumsq
__device__ u64   g_w2p[16*2048];                 // folded conv2 weights (o, cpair) packed
__device__ float g_b2[16*32];                    // folded conv2 bias

// ============ k_tr: lowres (n,ci,y,x) planar -> g_tr (n,y,x,ci) channel-last ====
__global__ __launch_bounds__(256) void k_tr(const float* __restrict__ lo){
    __shared__ float s[64][133];
    int n = blockIdx.x >> 7, y = blockIdx.x & 127;
    const float* inb = lo + (size_t)n*64*128*128 + (size_t)y*128;
    for (int i = threadIdx.x; i < 64*32; i += 256){
        int ci = i >> 5, x4 = (i & 31) * 4;
        float4 v = *(const float4*)(inb + (size_t)ci*16384 + x4);
        s[ci][x4] = v.x; s[ci][x4+1] = v.y; s[ci][x4+2] = v.z; s[ci][x4+3] = v.w;
    }
    __syncthreads();
    float* outb = g_tr + ((size_t)(n*128 + y)*128)*64;
    for (int i = threadIdx.x; i < 128*16; i += 256){
        int x = i >> 4, c4 = (i & 15) * 4;
        float4 v = make_float4(s[c4][x], s[c4+1][x], s[c4+2][x], s[c4+3][x]);
        *(float4*)(outb + x*64 + c4) = v;
    }
}

// ============ k_conv1: 1x1 conv (64->128) at LOW res, f32x2 =====================
// grid (2048, 2): (n*128+y, o-half). 256 thr = 64 pxgroups(2px) x 4 ogroups(16o)
__global__ __launch_bounds__(256) void k_conv1(const float* __restrict__ w1,
                                               const float* __restrict__ bias){
    __shared__ __align__(16) u64 ws[2048];   // 64 o x 32 cpairs
    int n = blockIdx.x >> 7, y = blockIdx.x & 127, oh = blockIdx.y;
    const u64* w64 = (const u64*)w1;         // conv1_w (128,64) row-major: pairs contiguous
    for (int i = threadIdx.x; i < 2048; i += 256) ws[i] = w64[oh*2048 + i];
    __syncthreads();
    int pxg = threadIdx.x >> 2, og = threadIdx.x & 3;
    const float* inb = g_tr + ((size_t)(n*128 + y)*128 + pxg*2)*64;
    u64 acc[2][16];
    #pragma unroll
    for (int p = 0; p < 2; p++)
        #pragma unroll
        for (int j = 0; j < 16; j++) acc[p][j] = 0ull;
    #pragma unroll 4
    for (int c = 0; c < 64; c += 4){
        F4U a0, a1;
        a0.f = *(const float4*)(inb + c);
        a1.f = *(const float4*)(inb + 64 + c);
        int cp = c >> 1;
        #pragma unroll
        for (int j = 0; j < 16; j++){
            ulonglong2 wv = *(const ulonglong2*)&ws[(og*16 + j)*32 + cp];
            ffma2(acc[0][j], a0.u[0], wv.x); ffma2(acc[0][j], a0.u[1], wv.y);
            ffma2(acc[1][j], a1.u[0], wv.x); ffma2(acc[1][j], a1.u[1], wv.y);
        }
    }
    int obase = oh*64 + og*16;
    float* outb = g_tl + ((size_t)(n*128 + y)*128 + pxg*2)*128 + obase;
    #pragma unroll
    for (int p = 0; p < 2; p++){
        float res[16];
        #pragma unroll
        for (int j = 0; j < 16; j++){
            float2 f = up2(acc[p][j]);
            res[j] = f.x + f.y + __ldg(&bias[obase + j]);
        }
        #pragma unroll
        for (int j4 = 0; j4 < 4; j4++)
            *(float4*)(outb + p*128 + j4*4) =
                make_float4(res[j4*4], res[j4*4+1], res[j4*4+2], res[j4*4+3]);
    }
}

// ============ k_up: bilinear 128->256 (align_corners) + exact GELU + partial stats
// grid 4096 = (n, oy). 256 thr: c = tid&127, x-half = tid>>7
__global__ __launch_bounds__(256) void k_up(){
    __shared__ int   x0s[256], x1s[256];
    __shared__ float wxs[256];
    __shared__ float sm[256];
    int n = blockIdx.x >> 8, oy = blockIdx.x & 255;
    {
        int ox = threadIdx.x;
        float xs = ox * (127.0f/255.0f);
        float xf = floorf(xs);
        int x0 = (int)xf;
        x0s[ox] = x0; x1s[ox] = min(x0 + 1, 127); wxs[ox] = xs - xf;
    }
    __syncthreads();
    float ysf = oy * (127.0f/255.0f);
    float yf  = floorf(ysf);
    int y0 = (int)yf, y1 = min(y0 + 1, 127);
    float wy = ysf - yf;
    int c = threadIdx.x & 127, half = threadIdx.x >> 7;
    const float* r0 = g_tl + ((size_t)(n*128 + y0)*128)*128 + c;
    const float* r1 = g_tl + ((size_t)(n*128 + y1)*128)*128 + c;
    float* outb = g_r + ((size_t)(n*256 + oy)*256)*128 + c;
    float s1 = 0.f, s2 = 0.f;
    for (int i = 0; i < 128; i++){
        int ox = half*128 + i;
        int x0 = x0s[ox], x1 = x1s[ox]; float wx = wxs[ox];
        float v0 = __ldg(r0 + (size_t)x0*128)*(1.f - wx) + __ldg(r0 + (size_t)x1*128)*wx;
        float v1 = __ldg(r1 + (size_t)x0*128)*(1.f - wx) + __ldg(r1 + (size_t)x1*128)*wx;
        float v  = v0*(1.f - wy) + v1*wy;
        float ge = 0.5f*v*(1.f + erff(v*0.70710678118654752f));
        outb[(size_t)ox*128] = ge;
        s1 += ge; s2 += ge*ge;
    }
    sm[threadIdx.x] = s1; __syncthreads();
    if (half == 0) g_p1[((size_t)n*256 + oy)*128 + c] = sm[c] + sm[c+128];
    __syncthreads();
    sm[threadIdx.x] = s2; __syncthreads();
    if (half == 0) g_p2[((size_t)n*256 + oy)*128 + c] = sm[c] + sm[c+128];
}

// ============ k_stats: GN stats + SE + fold into conv2 weights/bias ============
__global__ __launch_bounds__(256) void k_stats(const float* __restrict__ gnw,
        const float* __restrict__ gnb, const float* __restrict__ sw1,
        const float* __restrict__ sw2, const float* __restrict__ w2){
    int n = blockIdx.x;
    __shared__ float sc[256];
    __shared__ float sum[128], ssq[128], mr[128], Aa[128], Bb[128], y1s[16], mu[2], inv[2];
    int c = threadIdx.x & 127, half = threadIdx.x >> 7;
    float a = 0.f;
    for (int r = half*128; r < half*128 + 128; r++) a += g_p1[((size_t)n*256 + r)*128 + c];
    sc[threadIdx.x] = a; __syncthreads();
    if (half == 0) sum[c] = sc[c] + sc[c+128];
    __syncthreads();
    a = 0.f;
    for (int r = half*128; r < half*128 + 128; r++) a += g_p2[((size_t)n*256 + r)*128 + c];
    sc[threadIdx.x] = a; __syncthreads();
    if (half == 0) ssq[c] = sc[c] + sc[c+128];
    __syncthreads();
    if (threadIdx.x < 2){
        float S = 0.f, Q = 0.f;
        for (int i = 0; i < 64; i++){ S += sum[threadIdx.x*64 + i]; Q += ssq[threadIdx.x*64 + i]; }
        float mean = S * (1.f/(64.f*65536.f));
        float var  = Q * (1.f/(64.f*65536.f)) - mean*mean;
        mu[threadIdx.x] = mean; inv[threadIdx.x] = rsqrtf(var + 1e-5f);
    }
    __syncthreads();
    if (half == 0){
        int g = c >> 6;
        float mc = sum[c] * (1.f/65536.f);
        mr[c] = (mc - mu[g]) * inv[g] * gnw[c] + gnb[c];   // mean over HW of GN output
    }
    __syncthreads();
    if (threadIdx.x < 16){
        float acc = 0.f;
        for (int i = 0; i < 128; i++) acc += mr[i] * sw1[threadIdx.x*128 + i];
        y1s[threadIdx.x] = fmaxf(acc, 0.f);
    }
    __syncthreads();
    if (half == 0){
        float t = 0.f;
        for (int j = 0; j < 16; j++) t += y1s[j] * sw2[c*16 + j];
        float sg = 1.f/(1.f + expf(-t));
        int g = c >> 6;
        Aa[c] = inv[g]*gnw[c]*sg;
        Bb[c] = (gnb[c] - mu[g]*inv[g]*gnw[c])*sg;
    }
    __syncthreads();
    for (int i = threadIdx.x; i < 2048; i += 256){
        int o = i >> 6, cp = i & 63, c0 = cp*2;
        g_w2p[n*2048 + i] = pk2(w2[o*128 + c0]*Aa[c0], w2[o*128 + c0 + 1]*Aa[c0 + 1]);
    }
    if (threadIdx.x < 32){
        float bb = 0.f;
        for (int i = 0; i < 128; i++) bb += w2[threadIdx.x*128 + i] * Bb[i];
        g_b2[n*32 + threadIdx.x] = bb;
    }
}

// ============ k_conv2: folded 1x1 conv (128->32), f32x2 =========================
// grid 4096 = (n, y). 256 thr = 64 pxgroups(4px) x 4 ogroups(8o)
__global__ __launch_bounds__(256) void k_conv2(){
    __shared__ __align__(16) u64 ws[2048];   // 32 o x 64 cpairs
    __shared__ float bs[32];
    int n = blockIdx.x >> 8, y = blockIdx.x & 255;
    for (int i = threadIdx.x; i < 2048; i += 256) ws[i] = g_w2p[n*2048 + i];
    if (threadIdx.x < 32) bs[threadIdx.x] = g_b2[n*32 + threadIdx.x];
    __syncthreads();
    int pxg = threadIdx.x >> 2, og = threadIdx.x & 3;
    const float* inb = g_r + ((size_t)(n*256 + y)*256 + pxg*4)*128;
    u64 acc[4][8];
    #pragma unroll
    for (int p = 0; p < 4; p++)
        #pragma unroll
        for (int j = 0; j < 8; j++) acc[p][j] = 0ull;
    #pragma unroll 2
    for (int c = 0; c < 128; c += 4){
        F4U a[4];
        #pragma unroll
        for (int p = 0; p < 4; p++) a[p].f = *(const float4*)(inb + p*128 + c);
        int cp = c >> 1;
        #pragma unroll
        for (int j = 0; j < 8; j++){
            ulonglong2 wv = *(const ulonglong2*)&ws[(og*8 + j)*64 + cp];
            #pragma unroll
            for (int p = 0; p < 4; p++){
                ffma2(acc[p][j], a[p].u[0], wv.x);
                ffma2(acc[p][j], a[p].u[1], wv.y);
            }
        }
    }
    int x0 = pxg*4;
    #pragma unroll
    for (int j = 0; j < 8; j++){
        int o = og*8 + j;
        float bb = bs[o];
        float2 f0 = up2(acc[0][j]), f1 = up2(acc[1][j]), f2 = up2(acc[2][j]), f3 = up2(acc[3][j]);
        float4 r4 = make_float4(f0.x+f0.y+bb, f1.x+f1.y+bb, f2.x+f2.y+bb, f3.x+f3.y+bb);
        *(float4*)(g_lg + ((size_t)(n*32 + o)*256 + y)*256 + x0) = r4;
    }
}

// ============ k_softx: per-row softmax+cumsum (channel 2*hd) -> gy coord ========
// 8 rows per block (one per warp); lane owns 8 contiguous elems
__global__ __launch_bounds__(256) void k_softx(){
    int lane = threadIdx.x & 31, wid = threadIdx.x >> 5;
    int R = blockIdx.x*8 + wid;          // (p<<8)|y, p = n*16+hd
    int p = R >> 8, y = R & 255;
    int n = p >> 4, hd = p & 15;
    const float* src = g_lg + ((size_t)(n*32 + 2*hd)*256 + y)*256 + lane*8;
    float v[8];
    {
        float4 A = *(const float4*)src, B = *(const float4*)(src + 4);
        v[0]=A.x; v[1]=A.y; v[2]=A.z; v[3]=A.w;
        v[4]=B.x; v[5]=B.y; v[6]=B.z; v[7]=B.w;
    }
    float m = v[0];
    #pragma unroll
    for (int i = 1; i < 8; i++) m = fmaxf(m, v[i]);
    #pragma unroll
    for (int off = 16; off >= 1; off >>= 1) m = fmaxf(m, __shfl_xor_sync(FULL, m, off));
    float ls = 0.f;
    #pragma unroll
    for (int i = 0; i < 8; i++){ v[i] = expf(v[i] - m); ls += v[i]; }
    float pre = ls;
    #pragma unroll
    for (int off = 1; off < 32; off <<= 1){
        float t = __shfl_up_sync(FULL, pre, off);
        if (lane >= off) pre += t;
    }
    float total = __shfl_sync(FULL, pre, 31);
    float run = pre - ls;                 // exclusive prefix
    float sc = 255.f / total;
    float o[8];
    #pragma unroll
    for (int i = 0; i < 8; i++){ run += v[i]; o[i] = run * sc; }
    float* dst = g_gy + (size_t)p*65536 + y*256 + lane*8;
    *(float4*)dst       = make_float4(o[0], o[1], o[2], o[3]);
    *(float4*)(dst + 4) = make_float4(o[4], o[5], o[6], o[7]);
}

// ============ k_softy: per-column softmax+cumsum (channel 2*hd+1) -> gx coord ===
// block per (n,hd); thread = column x; 3 coalesced passes (L2-resident plane)
__global__ __launch_bounds__(256) void k_softy(){
    int pb = blockIdx.x;                  // p = n*16+hd
    int n = pb >> 4, hd = pb & 15;
    const float* src = g_lg + ((size_t)(n*32 + 2*hd + 1)*256)*256 + threadIdx.x;
    float m = -1e30f;
    for (int y = 0; y < 256; y++) m = fmaxf(m, __ldg(src + (size_t)y*256));
    float s = 0.f;
    for (int y = 0; y < 256; y++) s += expf(__ldg(src + (size_t)y*256) - m);
    float sc = 255.f / s, run = 0.f;
    float* dst = g_gx + (size_t)pb*65536 + threadIdx.x;
    for (int y = 0; y < 256; y++){
        run += expf(__ldg(src + (size_t)y*256) - m);
        dst[(size_t)y*256] = run * sc;
    }
}

// ============ k_sample: bilinear grid_sample (zeros pad, align_corners) =========
__global__ __launch_bounds__(256) void k_sample(const float* __restrict__ hi,
                                                float* __restrict__ out){
    int B = blockIdx.x;                   // (p<<8)|y
    int p = B >> 8, y = B & 255;
    size_t idx = (size_t)p*65536 + (size_t)y*256 + threadIdx.x;
    float gx = g_gx[idx], gy = g_gy[idx];
    float xf = floorf(gx), yf = floorf(gy);
    float wx = gx - xf, wy = gy - yf;
    int ix0 = (int)xf, iy0 = (int)yf;
    int ix1 = ix0 + 1, iy1 = iy0 + 1;
    float mx0 = (ix0 >= 0 && ix0 <= 255) ? 1.f : 0.f;
    float mx1 = (ix1 >= 0 && ix1 <= 255) ? 1.f : 0.f;
    float my0 = (iy0 >= 0 && iy0 <= 255) ? 1.f : 0.f;
    float my1 = (iy1 >= 0 && iy1 <= 255) ? 1.f : 0.f;
    int cx0 = min(max(ix0, 0), 255), cx1 = min(max(ix1, 0), 255);
    int cy0 = min(max(iy0, 0), 255), cy1 = min(max(iy1, 0), 255);
    const float* s = hi + (size_t)p*65536;
    float v00 = __ldg(s + (size_t)cy0*256 + cx0);
    float v10 = __ldg(s + (size_t)cy0*256 + cx1);
    float v01 = __ldg(s + (size_t)cy1*256 + cx0);
    float v11 = __ldg(s + (size_t)cy1*256 + cx1);
    out[idx] = v00*((1.f-wx)*(1.f-wy)*mx0*my0)
             + v10*(wx*(1.f-wy)*mx1*my0)
             + v01*((1.f-wx)*wy*mx0*my1)
             + v11*(wx*wy*mx1*my1);
}

// ================================ launch ========================================
extern "C" void kernel_launch(void* const* d_in, const int* in_sizes, int n_in,
                              void* d_out, int out_size){
    const float* lowres  = (const float*)d_in[0];
    const float* highres = (const float*)d_in[1];
    const float* conv1_w = (const float*)d_in[2];
    const float* conv1_b = (const float*)d_in[3];
    const float* gn_w    = (const float*)d_in[4];
    const float* gn_b    = (const float*)d_in[5];
    const float* se_w1   = (const float*)d_in[6];
    const float* se_w2   = (const float*)d_in[7];
    const float* conv2_w = (const float*)d_in[8];
    float* out = (float*)d_out;

    k_tr    <<<2048, 256>>>(lowres);
    k_conv1 <<<dim3(2048, 2), 256>>>(conv1_w, conv1_b);
    k_up    <<<4096, 256>>>();
    k_stats <<<16, 256>>>(gn_w, gn_b, se_w1, se_w2, conv2_w);
    k_conv2 <<<4096, 256>>>();
    k_softx <<<8192, 256>>>();
    k_softy <<<256, 256>>>();
    k_sample<<<65536, 256>>>(highres, out);
}